// round 14
// baseline (speedup 1.0000x reference)
#include <cuda_runtime.h>
#include <cuda_fp16.h>
#include <cstdint>

// ---------------- problem constants ----------------
constexpr int B_ = 16, C_ = 64, H_ = 128, W_ = 128, O_ = 128, KE_ = 9;
constexpr int HP = H_ + 2, WP = W_ + 2;      // padded x copy dims
constexpr int NTILES = B_ * H_;              // 2048 (1 output row per tile)
constexpr int NCTAS  = 296;                  // 148 SMs x 2 resident CTAs

// ---------------- device scratch (zero-init; halo stays 0) ----------------------
__device__ __align__(16) __half g_xh[(size_t)B_ * HP * WP * C_];
// w in MMA-fragment-major layout: [tap(9)][mblock(8)][ks(4)][lane(32)] -> uint4
__device__ __align__(16) uint4 g_wfrag[KE_ * 8 * 4 * 32];

// ---------------- smem layout: two x tile buffers -------------------------------
// x tile: [3 padded rows][130 cols] rows of 128B (c=64 fp16), SW128
constexpr int XROWS = 3 * 130;                   // 390
constexpr int XTILE = XROWS * 128;               // 49920
constexpr int SMEM_TOTAL = 2 * XTILE;            // 99840 -> 2 CTAs/SM = 195KB OK

__device__ __forceinline__ uint32_t sw(uint32_t off) { return off ^ ((off >> 3) & 0x70); }

__device__ __forceinline__ uint32_t smem_u32(const void* p) {
    uint32_t a;
    asm("{ .reg .u64 t; cvta.to.shared.u64 t, %1; cvt.u32.u64 %0, t; }" : "=r"(a) : "l"(p));
    return a;
}

__device__ __forceinline__ void cp16(uint32_t dst, const void* src) {
    asm volatile("cp.async.cg.shared.global [%0], [%1], 16;" :: "r"(dst), "l"(src));
}
#define CP_COMMIT() asm volatile("cp.async.commit_group;" ::: "memory")
#define CP_WAIT1()  asm volatile("cp.async.wait_group 1;" ::: "memory")
#define CP_WAIT0()  asm volatile("cp.async.wait_group 0;" ::: "memory")

__device__ __forceinline__ void ldsm4(uint32_t* r, uint32_t addr) {
    asm volatile("ldmatrix.sync.aligned.m8n8.x4.shared.b16 {%0,%1,%2,%3}, [%4];"
                 : "=r"(r[0]), "=r"(r[1]), "=r"(r[2]), "=r"(r[3]) : "r"(addr));
}

__device__ __forceinline__ void mma16816(float* d, const uint32_t* a, const uint32_t* b) {
    asm volatile(
        "mma.sync.aligned.m16n8k16.row.col.f32.f16.f16.f32 "
        "{%0,%1,%2,%3}, {%4,%5,%6,%7}, {%8,%9}, {%0,%1,%2,%3};"
        : "+f"(d[0]), "+f"(d[1]), "+f"(d[2]), "+f"(d[3])
        : "r"(a[0]), "r"(a[1]), "r"(a[2]), "r"(a[3]), "r"(b[0]), "r"(b[1]));
}

// ---------------- fused prep: x transpose + w fragment packing ------------------
constexpr int XBLOCKS = B_ * H_ * 4;   // 8192

__global__ __launch_bounds__(256, 4) void prep_kernel(const float* __restrict__ x,
                                                      const float* __restrict__ w) {
    if (blockIdx.x >= XBLOCKS) {
        // ---- w path: pack m16n8k16 A fragments ----
        int idx = (blockIdx.x - XBLOCKS) * 256 + threadIdx.x;   // 9216 total
        if (idx < KE_ * 1024) {
            int l  = idx & 31;
            int ks = (idx >> 5) & 3;
            int mb = (idx >> 7) & 7;
            int k  = idx >> 10;
            int gid = l >> 2, tg2 = (l & 3) * 2;
            int o0 = mb * 16 + gid;
            int c0 = ks * 16 + tg2;
            auto wv = [&](int o, int c) { return __float2half(w[(o * C_ + c) * KE_ + k]); };
            __align__(16) __half h[8];
            h[0] = wv(o0, c0);         h[1] = wv(o0, c0 + 1);
            h[2] = wv(o0 + 8, c0);     h[3] = wv(o0 + 8, c0 + 1);
            h[4] = wv(o0, c0 + 8);     h[5] = wv(o0, c0 + 9);
            h[6] = wv(o0 + 8, c0 + 8); h[7] = wv(o0 + 8, c0 + 9);
            g_wfrag[idx] = *(const uint4*)h;
        }
        return;
    }

    // ---- x path: padded NHWC fp16 via smem transpose (coalesced both sides) ----
    __shared__ __half sh[32][72];
    const int tid = threadIdx.x;
    const int wd = tid >> 5, l = tid & 31;
    const int blk = blockIdx.x;                  // b*H*4 + h*4 + wq
    const int wq = blk & 3;
    const int h  = (blk >> 2) & (H_ - 1);
    const int b  = blk >> 9;
    const int w0 = wq * 32;

    const float* src = x + (((size_t)b * C_ + wd) * H_ + h) * W_ + w0 + l;
    #pragma unroll
    for (int i = 0; i < 8; i++)
        sh[l][wd + i * 8] = __float2half(src[(size_t)(i * 8) * H_ * W_]);
    __syncthreads();

    const int pos = tid >> 3, chunk = tid & 7;
    size_t drow = ((size_t)(b * HP + h + 1) * WP + (w0 + pos + 1)) * C_ + chunk * 8;
    *(uint4*)(g_xh + drow) = *(const uint4*)&sh[pos][chunk * 8];
}

// ---------------- compute one tile (R10 straight-line body, fresh regs) ---------
__device__ __noinline__ void compute_tile(uint32_t xbase, float* __restrict__ out,
                                          int b, int h0) {
    const int tid = threadIdx.x;
    const int l = tid & 31, wid = tid >> 5;
    const int warpM = (wid >> 1) * 32;   // o offset: 0,32,64,96
    const int warpN = (wid & 1) * 64;    // w offset: 0,64
    const int brow  = (l & 7) + ((l >> 4) & 1) * 8;
    const int bcolb = ((l >> 3) & 1) * 16;

    float acc[2][8][4];
    #pragma unroll
    for (int mt = 0; mt < 2; mt++)
        #pragma unroll
        for (int nt = 0; nt < 8; nt++)
            #pragma unroll
            for (int q = 0; q < 4; q++) acc[mt][nt][q] = 0.0f;

    // base index into g_wfrag for this warp: [t][mb = warpM/16 + mt][ks][l]
    const uint4* wf = g_wfrag + (warpM >> 4) * 128 + l;

    #pragma unroll
    for (int t = 0; t < 9; t++) {                    // t = dh*3 + dw
        const int dh = t / 3, dw = t - dh * 3;
        const int browbase = dh * 130 + warpN + brow + dw;
        const uint4* wft = wf + t * 1024;

        #pragma unroll
        for (int ks = 0; ks < 4; ks++) {
            uint4 af[2];
            #pragma unroll
            for (int mt = 0; mt < 2; mt++)
                af[mt] = wft[mt * 128 + ks * 32];    // LDG.128, L1/L2-resident
            uint32_t bb[4][4];
            #pragma unroll
            for (int np = 0; np < 4; np++) {
                uint32_t rn = (uint32_t)(browbase + np * 16);
                ldsm4(bb[np], xbase + sw(rn * 128 + ks * 32 + bcolb));
            }
            #pragma unroll
            for (int mt = 0; mt < 2; mt++)
                #pragma unroll
                for (int np = 0; np < 4; np++) {
                    mma16816(acc[mt][2 * np],     (const uint32_t*)&af[mt], &bb[np][0]);
                    mma16816(acc[mt][2 * np + 1], (const uint32_t*)&af[mt], &bb[np][2]);
                }
        }
    }

    // ---- epilogue: fragment -> out[b][o][h0][w], streaming float2 stores ----
    const int gid = l >> 2, tg = l & 3;
    #pragma unroll
    for (int mt = 0; mt < 2; mt++)
        #pragma unroll
        for (int half = 0; half < 2; half++) {
            int o = warpM + mt * 16 + gid + half * 8;
            float* dst = out + (((size_t)b * O_ + o) * H_ + h0) * W_ + warpN + 2 * tg;
            #pragma unroll
            for (int nt = 0; nt < 8; nt++) {
                float2 v = make_float2(acc[mt][nt][half * 2], acc[mt][nt][half * 2 + 1]);
                __stcs((float2*)(dst + nt * 8), v);
            }
        }
}

// ---------------- main conv: persistent CTAs, cp.async double-buffered x --------
__global__ __launch_bounds__(256, 2)
void conv_mma_kernel(float* __restrict__ out) {
    extern __shared__ char smem[];
    const uint32_t sbase = smem_u32(smem);
    const int tid = threadIdx.x;
    const int cta = blockIdx.x;      // 0..NCTAS-1

    // stage tile tl (b = tl>>7, h0 = tl&127) into buffer bufs via cp.async
    auto stage = [&](int tl, int bufs) {
        int b = tl >> 7, h0 = tl & 127;
        const uint32_t dbase = sbase + bufs * XTILE;
        for (int idx = tid; idx < XROWS * 8; idx += 256) {
            int row = idx >> 3, chunk = idx & 7;
            int r = row / 130, wc = row - r * 130;
            const __half* src = g_xh + ((size_t)(b * HP + h0 + r) * WP + wc) * C_ + chunk * 8;
            cp16(dbase + sw(row * 128 + chunk * 16), src);
        }
        CP_COMMIT();
    };

    stage(cta, 0);
    int i = 0;
    for (int tl = cta; tl < NTILES; tl += NCTAS, i ^= 1) {
        int nxt = tl + NCTAS;
        if (nxt < NTILES) {
            stage(nxt, i ^ 1);       // next tile's DMA flies under this tile's MMAs
            CP_WAIT1();              // current buffer's group complete
        } else {
            CP_WAIT0();
        }
        __syncthreads();
        compute_tile(sbase + i * XTILE, out, tl >> 7, tl & 127);
        __syncthreads();             // readers done before buf is restaged (t+2)
    }
}

// ---------------- launch ----------------
extern "C" void kernel_launch(void* const* d_in, const int* in_sizes, int n_in,
                              void* d_out, int out_size) {
    const float* x = (const float*)d_in[0];
    const float* w = (const float*)d_in[1];
    float* out = (float*)d_out;

    cudaFuncSetAttribute(conv_mma_kernel, cudaFuncAttributeMaxDynamicSharedMemorySize,
                         SMEM_TOTAL);

    prep_kernel<<<XBLOCKS + 36, 256>>>(x, w);
    conv_mma_kernel<<<NCTAS, 256, SMEM_TOTAL>>>(out);
}

// round 15
// speedup vs baseline: 1.1298x; 1.1298x over previous
#include <cuda_runtime.h>
#include <cuda_fp16.h>
#include <cstdint>

// ---------------- problem constants ----------------
constexpr int B_ = 16, C_ = 64, H_ = 128, W_ = 128, O_ = 128, KE_ = 9;

// ---------------- device scratch ----------------
// w in MMA-fragment-major layout: [tap(9)][mblock(8)][ks(4)][lane(32)] -> uint4
__device__ __align__(16) uint4 g_wfrag[KE_ * 8 * 4 * 32];

// ---------------- smem layout (bytes): x tile only ----------------
// x tile: [3 padded rows][130 cols] rows of 128B (c=64 fp16), SW128
constexpr int XROWS = 3 * 130;                   // 390
constexpr int SMEM_TOTAL = XROWS * 128;          // 49920

__device__ __forceinline__ uint32_t sw(uint32_t off) { return off ^ ((off >> 3) & 0x70); }

__device__ __forceinline__ uint32_t smem_u32(const void* p) {
    uint32_t a;
    asm("{ .reg .u64 t; cvta.to.shared.u64 t, %1; cvt.u32.u64 %0, t; }" : "=r"(a) : "l"(p));
    return a;
}

__device__ __forceinline__ void ldsm4(uint32_t* r, uint32_t addr) {
    asm volatile("ldmatrix.sync.aligned.m8n8.x4.shared.b16 {%0,%1,%2,%3}, [%4];"
                 : "=r"(r[0]), "=r"(r[1]), "=r"(r[2]), "=r"(r[3]) : "r"(addr));
}

__device__ __forceinline__ void mma16816(float* d, const uint32_t* a, const uint32_t* b) {
    asm volatile(
        "mma.sync.aligned.m16n8k16.row.col.f32.f16.f16.f32 "
        "{%0,%1,%2,%3}, {%4,%5,%6,%7}, {%8,%9}, {%0,%1,%2,%3};"
        : "+f"(d[0]), "+f"(d[1]), "+f"(d[2]), "+f"(d[3])
        : "r"(a[0]), "r"(a[1]), "r"(a[2]), "r"(a[3]), "r"(b[0]), "r"(b[1]));
}

// ---------------- prep: w -> m16n8k16 A fragments (tiny) ------------------------
__global__ __launch_bounds__(256) void prep_w(const float* __restrict__ w) {
    int idx = blockIdx.x * 256 + threadIdx.x;   // KE*1024 = 9216 total
    if (idx < KE_ * 1024) {
        int l  = idx & 31;
        int ks = (idx >> 5) & 3;
        int mb = (idx >> 7) & 7;
        int k  = idx >> 10;
        int gid = l >> 2, tg2 = (l & 3) * 2;
        int o0 = mb * 16 + gid;
        int c0 = ks * 16 + tg2;
        auto wv = [&](int o, int c) { return __float2half(w[(o * C_ + c) * KE_ + k]); };
        __align__(16) __half h[8];
        h[0] = wv(o0, c0);         h[1] = wv(o0, c0 + 1);
        h[2] = wv(o0 + 8, c0);     h[3] = wv(o0 + 8, c0 + 1);
        h[4] = wv(o0, c0 + 8);     h[5] = wv(o0, c0 + 9);
        h[6] = wv(o0 + 8, c0 + 8); h[7] = wv(o0 + 8, c0 + 9);
        g_wfrag[idx] = *(const uint4*)h;
    }
}

// ---------------- main conv: M64xN32 warp tile (crossbar traffic halved) --------
__global__ __launch_bounds__(256, 2)
void conv_mma_kernel(const float* __restrict__ x, float* __restrict__ out) {
    extern __shared__ char smem[];
    const uint32_t sbase = smem_u32(smem);
    const int tid = threadIdx.x;
    const int l = tid & 31, wid = tid >> 5;
    const int warpM = (wid >> 2) * 64;   // o offset: 0,64   (4 mt blocks of 16)
    const int warpN = (wid & 3) * 32;    // w offset: 0,32,64,96 (2 np blocks of 16)
    const int h0 = blockIdx.x, b = blockIdx.y;

    // per-lane ldmatrix pieces for B
    const int brow  = (l & 7) + ((l >> 4) & 1) * 8;
    const int bcolb = ((l >> 3) & 1) * 16;

    // ---- prologue: convert+transpose x rows h0-1..h0+1 straight from NCHW fp32 --
    #pragma unroll
    for (int it = 0; it < 2; it++) {
        int row = tid + it * 256;
        if (row < XROWS) {
            int r = row / 130, wp = row - r * 130;
            int gh = h0 - 1 + r, gw = wp - 1;
            bool valid = ((unsigned)gh < (unsigned)H_) && ((unsigned)gw < (unsigned)W_);
            const float* src = x + (((size_t)b * C_) * H_ + gh) * (size_t)W_ + gw;
            const size_t cstride = (size_t)H_ * W_;
            uint32_t pk[32];
            #pragma unroll
            for (int j = 0; j < 32; j++) {
                float v0 = valid ? src[(2 * j) * cstride] : 0.0f;
                float v1 = valid ? src[(2 * j + 1) * cstride] : 0.0f;
                __half2 hh = __floats2half2_rn(v0, v1);
                pk[j] = *(const uint32_t*)&hh;
            }
            #pragma unroll
            for (int ch = 0; ch < 8; ch++) {
                uint4 v = make_uint4(pk[4 * ch], pk[4 * ch + 1], pk[4 * ch + 2], pk[4 * ch + 3]);
                *(uint4*)(smem + sw(row * 128 + ch * 16)) = v;
            }
        }
    }

    float acc[4][4][4];                  // [mt][nt = 2*np + half][quad]
    #pragma unroll
    for (int mt = 0; mt < 4; mt++)
        #pragma unroll
        for (int nt = 0; nt < 4; nt++)
            #pragma unroll
            for (int q = 0; q < 4; q++) acc[mt][nt][q] = 0.0f;

    // base index into g_wfrag for this warp: [t][mb = warpM/16 + mt][ks][l]
    const uint4* wf = g_wfrag + (warpM >> 4) * 128 + l;

    __syncthreads();   // x tile ready; the ONLY barrier in the kernel

    #pragma unroll
    for (int t = 0; t < 9; t++) {                    // t = dh*3 + dw
        const int dh = t / 3, dw = t - dh * 3;
        const int browbase = dh * 130 + warpN + brow + dw;
        const uint4* wft = wf + t * 1024;

        #pragma unroll
        for (int ks = 0; ks < 4; ks++) {
            uint4 af[4];
            #pragma unroll
            for (int mt = 0; mt < 4; mt++)
                af[mt] = wft[mt * 128 + ks * 32];    // LDG.128 via LSU (not crossbar)
            uint32_t bb[2][4];
            #pragma unroll
            for (int np = 0; np < 2; np++) {
                uint32_t rn = (uint32_t)(browbase + np * 16);
                ldsm4(bb[np], sbase + sw(rn * 128 + ks * 32 + bcolb));
            }
            #pragma unroll
            for (int mt = 0; mt < 4; mt++)
                #pragma unroll
                for (int np = 0; np < 2; np++) {
                    mma16816(acc[mt][2 * np],     (const uint32_t*)&af[mt], &bb[np][0]);
                    mma16816(acc[mt][2 * np + 1], (const uint32_t*)&af[mt], &bb[np][2]);
                }
        }
    }

    // ---- epilogue: fragment -> out[b][o][h0][w], float2 stores ----
    const int gid = l >> 2, tg = l & 3;
    #pragma unroll
    for (int mt = 0; mt < 4; mt++)
        #pragma unroll
        for (int half = 0; half < 2; half++) {
            int o = warpM + mt * 16 + gid + half * 8;
            float* dst = out + (((size_t)b * O_ + o) * H_ + h0) * W_ + warpN + 2 * tg;
            #pragma unroll
            for (int nt = 0; nt < 4; nt++) {
                float2 v = make_float2(acc[mt][nt][half * 2], acc[mt][nt][half * 2 + 1]);
                *(float2*)(dst + nt * 8) = v;
            }
        }
}

// ---------------- launch ----------------
extern "C" void kernel_launch(void* const* d_in, const int* in_sizes, int n_in,
                              void* d_out, int out_size) {
    const float* x = (const float*)d_in[0];
    const float* w = (const float*)d_in[1];
    float* out = (float*)d_out;

    cudaFuncSetAttribute(conv_mma_kernel, cudaFuncAttributeMaxDynamicSharedMemorySize,
                         SMEM_TOTAL);

    prep_w<<<36, 256>>>(w);
    conv_mma_kernel<<<dim3(H_, B_), 256, SMEM_TOTAL>>>(x, out);
}

// round 16
// speedup vs baseline: 1.1494x; 1.0173x over previous
#include <cuda_runtime.h>
#include <cuda_fp16.h>
#include <cstdint>

// ---------------- problem constants ----------------
constexpr int B_ = 16, C_ = 64, H_ = 128, W_ = 128, O_ = 128, KE_ = 9;

// ---------------- device scratch ----------------
// w in MMA-fragment-major layout: [tap(9)][mblock(8)][ks(4)][lane(32)] -> uint4
__device__ __align__(16) uint4 g_wfrag[KE_ * 8 * 4 * 32];

// ---------------- smem layout (bytes): x tile only ----------------
// x tile: [3 padded rows][130 cols] rows of 128B (c=64 fp16), SW128
constexpr int XROWS = 3 * 130;                   // 390
constexpr int SMEM_TOTAL = XROWS * 128;          // 49920

__device__ __forceinline__ uint32_t sw(uint32_t off) { return off ^ ((off >> 3) & 0x70); }

__device__ __forceinline__ uint32_t smem_u32(const void* p) {
    uint32_t a;
    asm("{ .reg .u64 t; cvta.to.shared.u64 t, %1; cvt.u32.u64 %0, t; }" : "=r"(a) : "l"(p));
    return a;
}

__device__ __forceinline__ void ldsm4(uint32_t* r, uint32_t addr) {
    asm volatile("ldmatrix.sync.aligned.m8n8.x4.shared.b16 {%0,%1,%2,%3}, [%4];"
                 : "=r"(r[0]), "=r"(r[1]), "=r"(r[2]), "=r"(r[3]) : "r"(addr));
}

__device__ __forceinline__ void mma16816(float* d, const uint32_t* a, const uint32_t* b) {
    asm volatile(
        "mma.sync.aligned.m16n8k16.row.col.f32.f16.f16.f32 "
        "{%0,%1,%2,%3}, {%4,%5,%6,%7}, {%8,%9}, {%0,%1,%2,%3};"
        : "+f"(d[0]), "+f"(d[1]), "+f"(d[2]), "+f"(d[3])
        : "r"(a[0]), "r"(a[1]), "r"(a[2]), "r"(a[3]), "r"(b[0]), "r"(b[1]));
}

// ---------------- prep: w -> m16n8k16 A fragments (tiny) ------------------------
__global__ __launch_bounds__(256) void prep_w(const float* __restrict__ w) {
    int idx = blockIdx.x * 256 + threadIdx.x;   // KE*1024 = 9216 total
    if (idx < KE_ * 1024) {
        int l  = idx & 31;
        int ks = (idx >> 5) & 3;
        int mb = (idx >> 7) & 7;
        int k  = idx >> 10;
        int gid = l >> 2, tg2 = (l & 3) * 2;
        int o0 = mb * 16 + gid;
        int c0 = ks * 16 + tg2;
        auto wv = [&](int o, int c) { return __float2half(w[(o * C_ + c) * KE_ + k]); };
        __align__(16) __half h[8];
        h[0] = wv(o0, c0);         h[1] = wv(o0, c0 + 1);
        h[2] = wv(o0 + 8, c0);     h[3] = wv(o0 + 8, c0 + 1);
        h[4] = wv(o0, c0 + 8);     h[5] = wv(o0, c0 + 9);
        h[6] = wv(o0 + 8, c0 + 8); h[7] = wv(o0 + 8, c0 + 9);
        g_wfrag[idx] = *(const uint4*)h;
    }
}

// ---------------- main conv: R10 body + per-tap batched A prefetch --------------
__global__ __launch_bounds__(256, 2)
void conv_mma_kernel(const float* __restrict__ x, float* __restrict__ out) {
    extern __shared__ char smem[];
    const uint32_t sbase = smem_u32(smem);
    const int tid = threadIdx.x;
    const int l = tid & 31, wid = tid >> 5;
    const int warpM = (wid >> 1) * 32;   // o offset: 0,32,64,96
    const int warpN = (wid & 1) * 64;    // w offset: 0,64
    const int h0 = blockIdx.x, b = blockIdx.y;

    // per-lane ldmatrix pieces for B
    const int brow  = (l & 7) + ((l >> 4) & 1) * 8;
    const int bcolb = ((l >> 3) & 1) * 16;

    // ---- prologue: convert+transpose x rows h0-1..h0+1 straight from NCHW fp32 --
    #pragma unroll
    for (int it = 0; it < 2; it++) {
        int row = tid + it * 256;
        if (row < XROWS) {
            int r = row / 130, wp = row - r * 130;
            int gh = h0 - 1 + r, gw = wp - 1;
            bool valid = ((unsigned)gh < (unsigned)H_) && ((unsigned)gw < (unsigned)W_);
            const float* src = x + (((size_t)b * C_) * H_ + gh) * (size_t)W_ + gw;
            const size_t cstride = (size_t)H_ * W_;
            uint32_t pk[32];
            #pragma unroll
            for (int j = 0; j < 32; j++) {
                float v0 = valid ? src[(2 * j) * cstride] : 0.0f;
                float v1 = valid ? src[(2 * j + 1) * cstride] : 0.0f;
                __half2 hh = __floats2half2_rn(v0, v1);
                pk[j] = *(const uint32_t*)&hh;
            }
            #pragma unroll
            for (int ch = 0; ch < 8; ch++) {
                uint4 v = make_uint4(pk[4 * ch], pk[4 * ch + 1], pk[4 * ch + 2], pk[4 * ch + 3]);
                *(uint4*)(smem + sw(row * 128 + ch * 16)) = v;
            }
        }
    }

    float acc[2][8][4];
    #pragma unroll
    for (int mt = 0; mt < 2; mt++)
        #pragma unroll
        for (int nt = 0; nt < 8; nt++)
            #pragma unroll
            for (int q = 0; q < 4; q++) acc[mt][nt][q] = 0.0f;

    // base index into g_wfrag for this warp: [t][mb = warpM/16 + mt][ks][l]
    const uint4* wf = g_wfrag + (warpM >> 4) * 128 + l;

    __syncthreads();   // x tile ready; the ONLY barrier in the kernel

    #pragma unroll
    for (int t = 0; t < 9; t++) {                    // t = dh*3 + dw
        const int dh = t / 3, dw = t - dh * 3;
        const int browbase = dh * 130 + warpN + brow + dw;
        const uint4* wft = wf + t * 1024;

        // batched A prefetch for the whole tap: 8 independent LDG.128 (MLP=8)
        uint4 af[2][4];                              // [mt][ks], 32 regs
        #pragma unroll
        for (int ks = 0; ks < 4; ks++)
            #pragma unroll
            for (int mt = 0; mt < 2; mt++)
                af[mt][ks] = wft[mt * 128 + ks * 32];

        #pragma unroll
        for (int ks = 0; ks < 4; ks++) {
            uint32_t bb[4][4];
            #pragma unroll
            for (int np = 0; np < 4; np++) {
                uint32_t rn = (uint32_t)(browbase + np * 16);
                ldsm4(bb[np], sbase + sw(rn * 128 + ks * 32 + bcolb));
            }
            #pragma unroll
            for (int mt = 0; mt < 2; mt++)
                #pragma unroll
                for (int np = 0; np < 4; np++) {
                    mma16816(acc[mt][2 * np],     (const uint32_t*)&af[mt][ks], &bb[np][0]);
                    mma16816(acc[mt][2 * np + 1], (const uint32_t*)&af[mt][ks], &bb[np][2]);
                }
        }
    }

    // ---- epilogue: fragment -> out[b][o][h0][w], streaming float2 stores --------
    const int gid = l >> 2, tg = l & 3;
    #pragma unroll
    for (int mt = 0; mt < 2; mt++)
        #pragma unroll
        for (int half = 0; half < 2; half++) {
            int o = warpM + mt * 16 + gid + half * 8;
            float* dst = out + (((size_t)b * O_ + o) * H_ + h0) * W_ + warpN + 2 * tg;
            #pragma unroll
            for (int nt = 0; nt < 8; nt++) {
                float2 v = make_float2(acc[mt][nt][half * 2], acc[mt][nt][half * 2 + 1]);
                __stcs((float2*)(dst + nt * 8), v);
            }
        }
}

// ---------------- launch ----------------
extern "C" void kernel_launch(void* const* d_in, const int* in_sizes, int n_in,
                              void* d_out, int out_size) {
    const float* x = (const float*)d_in[0];
    const float* w = (const float*)d_in[1];
    float* out = (float*)d_out;

    cudaFuncSetAttribute(conv_mma_kernel, cudaFuncAttributeMaxDynamicSharedMemorySize,
                         SMEM_TOTAL);

    prep_w<<<36, 256>>>(w);
    conv_mma_kernel<<<dim3(H_, B_), 256, SMEM_TOTAL>>>(x, out);
}